// round 2
// baseline (speedup 1.0000x reference)
#include <cuda_runtime.h>
#include <cuda_fp16.h>
#include <cstdint>

#define DI __device__ __forceinline__

// ---------------- problem dims ----------------
constexpr int Mdim = 16384;   // B*S
constexpr int Kdim = 2048;    // IN
constexpr int Ndim = 2048;    // OUT
constexpr int LR   = 128;     // L*R
constexpr int Rr   = 32;

// ---------------- scratch (device globals; no allocation allowed) ----------------
__device__ uint4 g_xh_raw[(size_t)Mdim * Kdim * 2 / 16];   // fp16 x      (64 MB)
__device__ uint4 g_wh_raw[(size_t)Ndim * Kdim * 2 / 16];   // fp16 W_eff  (8 MB)
__device__ float g_ut[LR * Ndim];                          // scaled U^T [k][o] (1 MB)

// ---------------- PTX helpers (family-portable only: no 'a' features) ----------------
DI uint32_t smem_u32(const void* p) {
    uint32_t a;
    asm("{ .reg .u64 t; cvta.to.shared.u64 t, %1; cvt.u32.u64 %0, t; }" : "=r"(a) : "l"(p));
    return a;
}
DI uint32_t swz128(uint32_t b) { return b ^ ((b >> 3) & 0x70); }

DI void cp_async16(uint32_t dst, const void* src) {
    asm volatile("cp.async.cg.shared.global [%0], [%1], 16;" :: "r"(dst), "l"(src) : "memory");
}
DI void cp_commit() { asm volatile("cp.async.commit_group;" ::: "memory"); }
template <int Nn> DI void cp_wait() { asm volatile("cp.async.wait_group %0;" :: "n"(Nn) : "memory"); }

DI void ldmatrix_x4(uint32_t* r, uint32_t addr) {
    asm volatile("ldmatrix.sync.aligned.m8n8.x4.shared.b16 {%0,%1,%2,%3}, [%4];"
                 : "=r"(r[0]), "=r"(r[1]), "=r"(r[2]), "=r"(r[3]) : "r"(addr));
}
DI void mma16816(float* c, const uint32_t* a, uint32_t b0, uint32_t b1) {
    asm volatile(
        "mma.sync.aligned.m16n8k16.row.col.f32.f16.f16.f32 "
        "{%0,%1,%2,%3}, {%4,%5,%6,%7}, {%8,%9}, {%0,%1,%2,%3};"
        : "+f"(c[0]), "+f"(c[1]), "+f"(c[2]), "+f"(c[3])
        : "r"(a[0]), "r"(a[1]), "r"(a[2]), "r"(a[3]), "r"(b0), "r"(b1));
}

// ============================================================
// Kernel 1: x (fp32) -> fp16
// ============================================================
__global__ void k_convert_x(const float* __restrict__ x) {
    size_t i = (size_t)blockIdx.x * blockDim.x + threadIdx.x;
    size_t stride = (size_t)gridDim.x * blockDim.x;
    const float4* x4 = (const float4*)x;
    uint2* o4 = (uint2*)g_xh_raw;
    const size_t n4 = (size_t)Mdim * Kdim / 4;
    for (; i < n4; i += stride) {
        float4 v = x4[i];
        __half2 a = __floats2half2_rn(v.x, v.y);
        __half2 b = __floats2half2_rn(v.z, v.w);
        uint2 u;
        u.x = *(uint32_t*)&a;
        u.y = *(uint32_t*)&b;
        o4[i] = u;
    }
}

// ============================================================
// Kernel 2: U_t[k][o] = scales[l] * ups[l][o][r],  k = l*32+r
// ============================================================
__global__ void k_build_ut(const float* __restrict__ ups, const float* __restrict__ scales) {
    int idx = blockIdx.x * 256 + threadIdx.x;   // 0 .. LR*Ndim-1
    int o = idx >> 7;
    int k = idx & 127;
    int l = k >> 5, r = k & 31;
    g_ut[k * Ndim + o] = scales[l] * ups[l * (Ndim * Rr) + o * Rr + r];
}

// ============================================================
// Kernel 3: W_eff = W + U_t^T @ D   (fp32 SIMT, K=128), store fp16
// ============================================================
__global__ void __launch_bounds__(256) k_weff(const float* __restrict__ weight,
                                              const float* __restrict__ downs) {
    extern __shared__ float wsm[];
    float* Us = wsm;             // [128][64]
    float* Ds = wsm + LR * 64;   // [128][64]
    const int O0 = blockIdx.y * 64, I0 = blockIdx.x * 64;
    const int tid = threadIdx.x;

    for (int c = tid; c < LR * 16; c += 256) {
        int k = c >> 4, f = c & 15;
        *(float4*)&Us[k * 64 + f * 4] = *(const float4*)&g_ut[k * Ndim + O0 + f * 4];
        *(float4*)&Ds[k * 64 + f * 4] = *(const float4*)&downs[k * Kdim + I0 + f * 4];
    }
    __syncthreads();

    const int to = tid >> 4, ti = tid & 15;
    float acc[4][4];
#pragma unroll
    for (int a = 0; a < 4; a++)
#pragma unroll
        for (int b = 0; b < 4; b++) acc[a][b] = 0.f;

#pragma unroll 4
    for (int k = 0; k < LR; k++) {
        float4 u = *(const float4*)&Us[k * 64 + to * 4];
        float4 d = *(const float4*)&Ds[k * 64 + ti * 4];
        float uu[4] = {u.x, u.y, u.z, u.w};
        float dd[4] = {d.x, d.y, d.z, d.w};
#pragma unroll
        for (int a = 0; a < 4; a++)
#pragma unroll
            for (int b = 0; b < 4; b++) acc[a][b] += uu[a] * dd[b];
    }

    __half* gw = (__half*)g_wh_raw;
#pragma unroll
    for (int a = 0; a < 4; a++) {
        int o = O0 + to * 4 + a;
        float4 wv = *(const float4*)&weight[(size_t)o * Kdim + I0 + ti * 4];
        __half2 p0 = __floats2half2_rn(acc[a][0] + wv.x, acc[a][1] + wv.y);
        __half2 p1 = __floats2half2_rn(acc[a][2] + wv.z, acc[a][3] + wv.w);
        uint2 u;
        u.x = *(uint32_t*)&p0;
        u.y = *(uint32_t*)&p1;
        *(uint2*)&gw[(size_t)o * Kdim + I0 + ti * 4] = u;
    }
}

// ============================================================
// Kernel 4: main GEMM  y[m][n] = sum_k xh[m][k] * wh[n][k] + bias[n]
//   mma.sync.m16n8k16, BM=128 BN=128 BK=64, 3-stage cp.async,
//   256 threads (8 warps 2x4, warp tile 64x32), SW128 swizzle.
// ============================================================
constexpr int BK = 64;
constexpr int STAGES = 3;
constexpr int NK = Kdim / BK;                    // 32
constexpr int AB_BYTES = 128 * 128;              // 16 KB (128 rows x 128 B)
constexpr int STG_BYTES = 2 * AB_BYTES;          // 32 KB
constexpr int GEMM_SMEM = STAGES * STG_BYTES;    // 96 KB

__global__ void __launch_bounds__(256, 2) k_gemm(const float* __restrict__ bias,
                                                 float* __restrict__ out) {
    extern __shared__ char smem[];
    const uint32_t sb = smem_u32(smem);
    const int tid = threadIdx.x;
    const int wid = tid >> 5, lane = tid & 31;
    const int M0 = blockIdx.y * 128, N0 = blockIdx.x * 128;

    const int warp_m = (wid & 1) * 64;     // 2 warps along M
    const int warp_n = (wid >> 1) * 32;    // 4 warps along N

    const __half* gA = (const __half*)g_xh_raw;
    const __half* gB = (const __half*)g_wh_raw;

    auto load_stage = [&](int s, int kk) {
        const uint32_t base = sb + s * STG_BYTES;
        const int k0 = kk * BK;
        // A: 128 rows x 8 chunks of 16B; 256 threads -> 4 iters
#pragma unroll
        for (int it = 0; it < 4; it++) {
            int c = tid + it * 256;
            int row = c >> 3, col = c & 7;
            cp_async16(base + swz128(row * 128 + col * 16),
                       gA + (size_t)(M0 + row) * Kdim + k0 + col * 8);
        }
        // B
#pragma unroll
        for (int it = 0; it < 4; it++) {
            int c = tid + it * 256;
            int row = c >> 3, col = c & 7;
            cp_async16(base + AB_BYTES + swz128(row * 128 + col * 16),
                       gB + (size_t)(N0 + row) * Kdim + k0 + col * 8);
        }
    };

    float acc[4][4][4];
#pragma unroll
    for (int mt = 0; mt < 4; mt++)
#pragma unroll
        for (int nt = 0; nt < 4; nt++)
#pragma unroll
            for (int c = 0; c < 4; c++) acc[mt][nt][c] = 0.f;

    // prologue
    load_stage(0, 0); cp_commit();
    load_stage(1, 1); cp_commit();

    const int lane15 = lane & 15;
    const int laneHi = lane >> 4;

    for (int k = 0; k < NK; k++) {
        cp_wait<STAGES - 2>();
        __syncthreads();

        const int kn = k + STAGES - 1;
        if (kn < NK) load_stage(kn % STAGES, kn);
        cp_commit();

        const int s = k % STAGES;
        const uint32_t Ab = sb + s * STG_BYTES;
        const uint32_t Bb = Ab + AB_BYTES;

#pragma unroll
        for (int ks = 0; ks < 4; ks++) {   // 4 x k16 per BK=64
            uint32_t a[4][4], b[2][4];
#pragma unroll
            for (int mt = 0; mt < 4; mt++) {
                int row = warp_m + mt * 16 + lane15;
                ldmatrix_x4(a[mt], Ab + swz128(row * 128 + (ks * 2 + laneHi) * 16));
            }
#pragma unroll
            for (int np = 0; np < 2; np++) {
                int row = warp_n + np * 16 + lane15;
                ldmatrix_x4(b[np], Bb + swz128(row * 128 + (ks * 2 + laneHi) * 16));
            }
#pragma unroll
            for (int mt = 0; mt < 4; mt++)
#pragma unroll
                for (int nt = 0; nt < 4; nt++) {
                    const int np = nt >> 1, half = nt & 1;
                    mma16816(acc[mt][nt], a[mt], b[np][half], b[np][2 + half]);
                }
        }
    }

    // epilogue: acc -> out with bias
    const int gq = lane >> 2, rq = lane & 3;
#pragma unroll
    for (int mt = 0; mt < 4; mt++) {
#pragma unroll
        for (int nt = 0; nt < 4; nt++) {
            int m = M0 + warp_m + mt * 16 + gq;
            int n = N0 + warp_n + nt * 8 + rq * 2;
            float2 bv = *(const float2*)&bias[n];
            float2 v0, v1;
            v0.x = acc[mt][nt][0] + bv.x;
            v0.y = acc[mt][nt][1] + bv.y;
            v1.x = acc[mt][nt][2] + bv.x;
            v1.y = acc[mt][nt][3] + bv.y;
            *(float2*)&out[(size_t)m * Ndim + n] = v0;
            *(float2*)&out[(size_t)(m + 8) * Ndim + n] = v1;
        }
    }
}

// ============================================================
// launch
// ============================================================
extern "C" void kernel_launch(void* const* d_in, const int* in_sizes, int n_in,
                              void* d_out, int out_size) {
    const float* x      = (const float*)d_in[0];
    const float* weight = (const float*)d_in[1];
    const float* bias   = (const float*)d_in[2];
    const float* downs  = (const float*)d_in[3];
    const float* ups    = (const float*)d_in[4];
    const float* scales = (const float*)d_in[5];
    float* out = (float*)d_out;

    cudaFuncSetAttribute(k_gemm, cudaFuncAttributeMaxDynamicSharedMemorySize, GEMM_SMEM);
    cudaFuncSetAttribute(k_weff, cudaFuncAttributeMaxDynamicSharedMemorySize, 2 * LR * 64 * 4);

    k_convert_x<<<4096, 256>>>(x);
    k_build_ut<<<(LR * Ndim) / 256, 256>>>(ups, scales);
    k_weff<<<dim3(Kdim / 64, Ndim / 64), 256, 2 * LR * 64 * 4>>>(weight, downs);
    k_gemm<<<dim3(Ndim / 128, Mdim / 128), 256, GEMM_SMEM>>>(bias, out);
}